// round 14
// baseline (speedup 1.0000x reference)
#include <cuda_runtime.h>
#include <cuda_fp16.h>
#include <cstdint>
#include <cstddef>

// Problem constants
#define D      256
#define NB     4
#define TSEQ   4096
#define MROWS  (NB * TSEQ)          // 16384
#define N_QKV  (3 * D)              // 768
#define SCALE  0.0625f              // 1/sqrt(256)

// Scratch (device globals — no allocation allowed)
__device__ __half g_qkv[(size_t)MROWS * N_QKV];    // qkv fp16 (q prescaled)
__device__ __half g_xh[(size_t)MROWS * D];         // x fp16
__device__ __half g_ch[(size_t)MROWS * D];         // ctx fp16
__device__ __half g_wqh[(size_t)N_QKV * D];        // W_qkv^T [n][k]
__device__ __half g_wph[(size_t)D * D];            // W_proj^T [n][k]
__device__ __half g_Oph[(size_t)3 * MROWS * D];    // partial O, fp16 (3 slots)
__device__ float  g_lp[(size_t)3 * MROWS];         // partial l

// ---------------------------------------------------------------------------
// helpers
// ---------------------------------------------------------------------------
__device__ __forceinline__ uint32_t smem_u32(const void* p) {
    return (uint32_t)__cvta_generic_to_shared(p);
}
__device__ __forceinline__ void ldsm4(uint32_t r[4], uint32_t addr) {
    asm volatile("ldmatrix.sync.aligned.m8n8.x4.shared.b16 {%0,%1,%2,%3}, [%4];"
        : "=r"(r[0]), "=r"(r[1]), "=r"(r[2]), "=r"(r[3]) : "r"(addr));
}
__device__ __forceinline__ void ldsm4t(uint32_t r[4], uint32_t addr) {
    asm volatile("ldmatrix.sync.aligned.m8n8.x4.trans.shared.b16 {%0,%1,%2,%3}, [%4];"
        : "=r"(r[0]), "=r"(r[1]), "=r"(r[2]), "=r"(r[3]) : "r"(addr));
}
__device__ __forceinline__ void mma16816(float d[4], const uint32_t a[4],
                                         uint32_t b0, uint32_t b1) {
    asm volatile(
        "mma.sync.aligned.m16n8k16.row.col.f32.f16.f16.f32 "
        "{%0,%1,%2,%3},{%4,%5,%6,%7},{%8,%9},{%0,%1,%2,%3};"
        : "+f"(d[0]), "+f"(d[1]), "+f"(d[2]), "+f"(d[3])
        : "r"(a[0]), "r"(a[1]), "r"(a[2]), "r"(a[3]), "r"(b0), "r"(b1));
}
__device__ __forceinline__ uint32_t pack_h2(__half a, __half b) {
    return (uint32_t)__half_as_ushort(a) |
           ((uint32_t)__half_as_ushort(b) << 16);
}

#define CP_ASYNC16(dst, src) \
    asm volatile("cp.async.cg.shared.global [%0], [%1], 16;\n" \
                 :: "r"(dst), "l"(src))
#define CP_COMMIT()  asm volatile("cp.async.commit_group;\n" ::)
#define CP_WAIT0()   asm volatile("cp.async.wait_group 0;\n" ::)
#define CP_WAIT1()   asm volatile("cp.async.wait_group 1;\n" ::)
#define CP_WAIT2()   asm volatile("cp.async.wait_group 2;\n" ::)

// ---------------------------------------------------------------------------
// merged prep kernel: x -> fp16, transpose both weights -> fp16 [n][k]
//   blocks [0,4096): x ; [4096,4192): W_qkv ; [4192,4224): W_proj
// ---------------------------------------------------------------------------
__global__ void prep_kernel(const float* __restrict__ x,
                            const float* __restrict__ Wq,
                            const float* __restrict__ Wp)
{
    const int b = blockIdx.x;
    const int tid = threadIdx.x;
    if (b < 4096) {
        size_t idx = (size_t)b * 256 + tid;
        float4 v = reinterpret_cast<const float4*>(x)[idx];
        uint32_t h0 = pack_h2(__float2half_rn(v.x), __float2half_rn(v.y));
        uint32_t h1 = pack_h2(__float2half_rn(v.z), __float2half_rn(v.w));
        reinterpret_cast<uint2*>(g_xh)[idx] = make_uint2(h0, h1);
        return;
    }
    const bool isq = (b < 4192);
    const float* W = isq ? Wq : Wp;
    __half* th = isq ? g_wqh : g_wph;
    const int N = isq ? N_QKV : D;
    int idx = (b - (isq ? 4096 : 4192)) * 256 + tid;
    if (idx >= N * 32) return;
    int n = idx >> 5;
    int k0 = (idx & 31) * 8;
    uint32_t h[4];
    #pragma unroll
    for (int p = 0; p < 4; p++) {
        float a = W[(size_t)(k0 + 2 * p) * N + n];
        float bb = W[(size_t)(k0 + 2 * p + 1) * N + n];
        h[p] = pack_h2(__float2half_rn(a), __float2half_rn(bb));
    }
    *reinterpret_cast<uint4*>(th + (size_t)n * D + k0) = make_uint4(h[0], h[1], h[2], h[3]);
}

// ---------------------------------------------------------------------------
// fp16 1-term GEMM: C = A * B^T + bias
//   BM=128, BN=128, BK=32, 4 stages, ONE barrier per K-step, 2 CTAs/SM.
//   mode 0: write fp16 qkv (q cols prescaled); mode 1: write fp32 out (width N)
// ---------------------------------------------------------------------------
#define GST2 40
#define QA_ELEMS (128 * GST2)
#define QB_ELEMS (128 * GST2)
#define Q_STAGE (QA_ELEMS + QB_ELEMS)
#define QKV_SMEM_BYTES (4 * Q_STAGE * 2)       // 81920 B

__global__ __launch_bounds__(256, 2) void gemm_1t_kernel(
    const __half* __restrict__ Ah_g, const __half* __restrict__ Bh_g,
    const float* __restrict__ bias, float* __restrict__ outp,
    int N, int mode)
{
    extern __shared__ __half sq[];
    const int tid  = threadIdx.x;
    const int lane = tid & 31;
    const int wid  = tid >> 5;
    const int wr   = wid >> 1;
    const int wc   = wid & 1;
    const int qr   = lane >> 2;
    const int qc   = lane & 3;

    const int m0 = blockIdx.y * 128;
    const int n0 = blockIdx.x * 128;

    const uint32_t sm_b = smem_u32(sq);

    auto issue = [&](int s, int kb) {
        const int k0 = kb * 32;
        __half* Ah_s = sq + (size_t)s * Q_STAGE;
        __half* Bh_s = Ah_s + QA_ELEMS;
        #pragma unroll
        for (int t = 0; t < 2; t++) {
            int i = tid + t * 256;
            int r = i >> 2;
            int c8 = (i & 3) * 8;
            size_t ga = (size_t)(m0 + r) * D + k0 + c8;
            size_t gbo = (size_t)(n0 + r) * D + k0 + c8;
            CP_ASYNC16(smem_u32(Ah_s + r * GST2 + c8), Ah_g + ga);
            CP_ASYNC16(smem_u32(Bh_s + r * GST2 + c8), Bh_g + gbo);
        }
        CP_COMMIT();
    };

    float acc[2][8][4];
    #pragma unroll
    for (int mt = 0; mt < 2; mt++)
        #pragma unroll
        for (int nt = 0; nt < 8; nt++)
            #pragma unroll
            for (int j = 0; j < 4; j++) acc[mt][nt][j] = 0.0f;

    const int b_row = ((lane >> 4) & 1) * 8 + (lane & 7);
    const int b_cg  = ((lane >> 3) & 1) * 8;

    issue(0, 0);
    issue(1, 1);
    #pragma unroll
    for (int kb = 0; kb < 8; kb++) {
        const int cur = kb & 3;
        if (kb + 2 < 8) issue((kb + 2) & 3, kb + 2);
        if (kb <= 5)      { CP_WAIT2(); }
        else if (kb == 6) { CP_WAIT1(); }
        else              { CP_WAIT0(); }
        __syncthreads();     // single barrier per K-step (4-stage ring)

        const uint32_t Ah_b = sm_b + (uint32_t)cur * (Q_STAGE * 2);
        const uint32_t Bh_b = Ah_b + QA_ELEMS * 2;

        #pragma unroll
        for (int ks = 0; ks < 2; ks++) {
            uint32_t ah[2][4];
            #pragma unroll
            for (int mt = 0; mt < 2; mt++) {
                int a_off = (wr * 32 + mt * 16 + (lane & 15)) * GST2
                            + (lane >> 4) * 8 + ks * 16;
                ldsm4(ah[mt], Ah_b + (uint32_t)a_off * 2);
            }
            #pragma unroll
            for (int np = 0; np < 4; np++) {
                int koff = (wc * 64 + np * 16 + b_row) * GST2 + ks * 16 + b_cg;
                uint32_t bh[4];
                ldsm4(bh, Bh_b + (uint32_t)koff * 2);
                #pragma unroll
                for (int mt = 0; mt < 2; mt++) {
                    mma16816(acc[mt][2 * np],     ah[mt], bh[0], bh[1]);
                    mma16816(acc[mt][2 * np + 1], ah[mt], bh[2], bh[3]);
                }
            }
        }
    }

    #pragma unroll
    for (int mt = 0; mt < 2; mt++) {
        const int rA = m0 + wr * 32 + mt * 16 + qr;
        const int rB = rA + 8;
        #pragma unroll
        for (int nt = 0; nt < 8; nt++) {
            const int gc = n0 + wc * 64 + nt * 8 + qc * 2;
            const float b0 = bias[gc], b1 = bias[gc + 1];
            float v00 = acc[mt][nt][0] + b0;
            float v01 = acc[mt][nt][1] + b1;
            float v10 = acc[mt][nt][2] + b0;
            float v11 = acc[mt][nt][3] + b1;
            if (mode == 0) {
                if (gc < 256) { v00 *= SCALE; v01 *= SCALE; v10 *= SCALE; v11 *= SCALE; }
                uint32_t hA = pack_h2(__float2half_rn(v00), __float2half_rn(v01));
                uint32_t hB = pack_h2(__float2half_rn(v10), __float2half_rn(v11));
                *reinterpret_cast<uint32_t*>(g_qkv + (size_t)rA * N_QKV + gc) = hA;
                *reinterpret_cast<uint32_t*>(g_qkv + (size_t)rB * N_QKV + gc) = hB;
            } else {
                *reinterpret_cast<float2*>(outp + (size_t)rA * N + gc) = make_float2(v00, v01);
                *reinterpret_cast<float2*>(outp + (size_t)rB * N + gc) = make_float2(v10, v11);
            }
        }
    }
}

// ---------------------------------------------------------------------------
// FA2-style fp16 flash attention (R9 core), BN=64, 2 CTAs/SM, split-KV x3.
// fp16 partial O output. smem: Qh/Kh/Vh 64x264 + Ps 64x72 + lred = 111 KB.
// ---------------------------------------------------------------------------
#define QST 264
#define KST 264
#define VST 264
#define PST 72
#define ATTN_SMEM_BYTES ((3 * 64 * 264 + 64 * PST) * 2 + 512)

__global__ __launch_bounds__(256, 2) void attn_kernel()
{
    extern __shared__ __half sm[];
    __half* Qh = sm;
    __half* Kh = Qh + 64 * QST;
    __half* Vh = Kh + 64 * KST;
    __half* Ps = Vh + 64 * VST;
    float* lred = reinterpret_cast<float*>(Ps + 64 * PST);   // [2][64]

    const int tid  = threadIdx.x;
    const int lane = tid & 31;
    const int wid  = tid >> 5;
    const int wr   = wid & 3;
    const int ch   = wid >> 2;
    const int qr   = lane >> 2;
    const int qc   = lane & 3;

    // LPT: heaviest q-tiles first. 768 CTAs = 64 qtiles x 4 batches x 3 parts
    const int bid   = blockIdx.x;
    const int it    = 63 - (bid / 12);
    const int inner = bid % 12;
    const int batch = inner & 3;
    const int part  = inner >> 2;             // 0..2
    const int i0    = it * 64;
    const int nch   = it + 1;
    const int base  = nch / 3, rem = nch % 3;
    const int cnt   = base + (part < rem ? 1 : 0);
    const int s_beg = part * base + (part < rem ? part : rem);
    const int s_end = s_beg + cnt;

    const size_t gb = (size_t)batch * TSEQ * N_QKV;

    auto issueK = [&](int j) {
        const __half* gk = g_qkv + gb + (size_t)j * 64 * N_QKV + 256;
        #pragma unroll
        for (int t = 0; t < 8; t++) {
            int i = tid + t * 256;
            int r = i >> 5, c = (i & 31) * 8;
            CP_ASYNC16(smem_u32(Kh + r * KST + c), gk + (size_t)r * N_QKV + c);
        }
        CP_COMMIT();
    };
    auto issueV = [&](int j) {
        const __half* gv = g_qkv + gb + (size_t)j * 64 * N_QKV + 512;
        #pragma unroll
        for (int t = 0; t < 8; t++) {
            int i = tid + t * 256;
            int r = i >> 5, c = (i & 31) * 8;
            CP_ASYNC16(smem_u32(Vh + r * VST + c), gv + (size_t)r * N_QKV + c);
        }
        CP_COMMIT();
    };

    const bool nonempty = (s_beg < s_end);

    if (nonempty) {
        const __half* gq = g_qkv + gb + (size_t)i0 * N_QKV;
        #pragma unroll
        for (int t = 0; t < 8; t++) {
            int i = tid + t * 256;
            int r = i >> 5, c = (i & 31) * 8;
            CP_ASYNC16(smem_u32(Qh + r * QST + c), gq + (size_t)r * N_QKV + c);
        }
        CP_COMMIT();
        issueK(s_beg);
        issueV(s_beg);
    }

    const uint32_t Qh_b = smem_u32(Qh);
    const uint32_t Kh_b = smem_u32(Kh);
    const uint32_t Vh_b = smem_u32(Vh);
    const uint32_t Ps_b = smem_u32(Ps);

    const int a_off = (wr * 16 + (lane & 15)) * QST + (lane >> 4) * 8;
    const int p_off = (wr * 16 + (lane & 15)) * PST + (lane >> 4) * 8;
    const int b_row = ((lane >> 4) & 1) * 8 + (lane & 7);
    const int b_cg  = ((lane >> 3) & 1) * 8;
    const int v_row = ((lane >> 3) & 1) * 8 + (lane & 7);
    const int v_cg  = (lane >> 4) * 8;

    float O[16][4];
    #pragma unroll
    for (int t = 0; t < 16; t++)
        #pragma unroll
        for (int j = 0; j < 4; j++) O[t][j] = 0.0f;
    float l0 = 0.0f, l1 = 0.0f;

    const int lr0  = wr * 16 + qr;
    const int row0 = i0 + lr0;
    const int row1 = row0 + 8;

    for (int s = s_beg; s < s_end; s++) {
        const bool hasNext = (s + 1 < s_end);

        CP_WAIT1();
        __syncthreads();

        // ---- S = Qh Kh^T ----
        float sacc[4][4];
        #pragma unroll
        for (int t = 0; t < 4; t++)
            #pragma unroll
            for (int j = 0; j < 4; j++) sacc[t][j] = 0.0f;

        #pragma unroll 8
        for (int ks = 0; ks < 16; ks++) {
            uint32_t ah[4];
            ldsm4(ah, Qh_b + (uint32_t)(a_off + ks * 16) * 2);
            #pragma unroll
            for (int tp = 0; tp < 2; tp++) {
                uint32_t koff = (uint32_t)((ch * 32 + tp * 16 + b_row) * KST
                                           + ks * 16 + b_cg) * 2;
                uint32_t bh[4];
                ldsm4(bh, Kh_b + koff);
                mma16816(sacc[2 * tp],     ah, bh[0], bh[1]);
                mma16816(sacc[2 * tp + 1], ah, bh[2], bh[3]);
            }
        }
        __syncthreads();
        if (hasNext) issueK(s + 1);

        // ---- exp (no max), causal mask on diag chunk, write P to smem ----
        const bool diag = (s == it);
        #pragma unroll
        for (int nt = 0; nt < 4; nt++) {
            const int cl = ch * 32 + nt * 8 + qc * 2;
            const int c0 = s * 64 + cl;
            float p0 = (diag && (c0     > row0)) ? 0.0f : __expf(sacc[nt][0]);
            float p1 = (diag && (c0 + 1 > row0)) ? 0.0f : __expf(sacc[nt][1]);
            float p2 = (diag && (c0     > row1)) ? 0.0f : __expf(sacc[nt][2]);
            float p3 = (diag && (c0 + 1 > row1)) ? 0.0f : __expf(sacc[nt][3]);
            l0 += p0 + p1;
            l1 += p2 + p3;
            *reinterpret_cast<uint32_t*>(Ps + lr0 * PST + cl) =
                pack_h2(__float2half_rn(p0), __float2half_rn(p1));
            *reinterpret_cast<uint32_t*>(Ps + (lr0 + 8) * PST + cl) =
                pack_h2(__float2half_rn(p2), __float2half_rn(p3));
        }

        if (hasNext) { CP_WAIT1(); } else { CP_WAIT0(); }
        __syncthreads();

        // ---- O += P V ----
        uint32_t aP[4][4];
        #pragma unroll
        for (int ks = 0; ks < 4; ks++)
            ldsm4(aP[ks], Ps_b + (uint32_t)(p_off + ks * 16) * 2);

        #pragma unroll
        for (int ks = 0; ks < 4; ks++) {
            #pragma unroll
            for (int nt = 0; nt < 8; nt++) {
                uint32_t voff = (uint32_t)((ks * 16 + v_row) * VST
                                           + ch * 128 + nt * 16 + v_cg) * 2;
                uint32_t bh[4];
                ldsm4t(bh, Vh_b + voff);
                mma16816(O[2 * nt],     aP[ks], bh[0], bh[1]);
                mma16816(O[2 * nt + 1], aP[ks], bh[2], bh[3]);
            }
        }
        __syncthreads();
        if (hasNext) issueV(s + 1);
    }

    // ---- epilogue: l cross-half reduce; fp16 partial O direct write ----
    l0 += __shfl_xor_sync(0xffffffffu, l0, 1);
    l0 += __shfl_xor_sync(0xffffffffu, l0, 2);
    l1 += __shfl_xor_sync(0xffffffffu, l1, 1);
    l1 += __shfl_xor_sync(0xffffffffu, l1, 2);
    __syncthreads();
    if (qc == 0) { lred[ch * 64 + lr0] = l0; lred[ch * 64 + lr0 + 8] = l1; }
    __syncthreads();

    __half* dst = g_Oph + ((size_t)part * MROWS + (size_t)batch * TSEQ) * D;
    #pragma unroll
    for (int nt = 0; nt < 16; nt++) {
        int col = ch * 128 + nt * 8 + qc * 2;
        *reinterpret_cast<uint32_t*>(dst + (size_t)row0 * D + col) =
            pack_h2(__float2half_rn(O[nt][0]), __float2half_rn(O[nt][1]));
        *reinterpret_cast<uint32_t*>(dst + (size_t)row1 * D + col) =
            pack_h2(__float2half_rn(O[nt][2]), __float2half_rn(O[nt][3]));
    }
    if (ch == 0 && qc == 0) {
        g_lp[(size_t)part * MROWS + batch * TSEQ + row0] = lred[lr0] + lred[64 + lr0];
        g_lp[(size_t)part * MROWS + batch * TSEQ + row1] = lred[lr0 + 8] + lred[64 + lr0 + 8];
    }
}

// ---------------------------------------------------------------------------
// combine: ctx = (O0+O1+O2)/(l0+l1+l2) -> fp16 plane (fp16 partial reads)
// ---------------------------------------------------------------------------
__global__ void combine_kernel()
{
    size_t idx = (size_t)blockIdx.x * 256 + threadIdx.x;   // one per 8 cols
    size_t row = idx >> 5;
    int c8 = (int)(idx & 31) * 8;
    float acc[8] = {};
    #pragma unroll
    for (int sl = 0; sl < 3; sl++) {
        uint4 v = *reinterpret_cast<const uint4*>(
            g_Oph + (size_t)sl * MROWS * D + row * D + c8);
        const uint32_t w[4] = {v.x, v.y, v.z, v.w};
        #pragma unroll
        for (int p = 0; p < 4; p++) {
            __half2 h2 = *reinterpret_cast<const __half2*>(&w[p]);
            float2 f2 = __half22float2(h2);
            acc[2 * p]     += f2.x;
            acc[2 * p + 1] += f2.y;
        }
    }
    float inv = 1.0f / (g_lp[row] + g_lp[MROWS + row] + g_lp[2 * (size_t)MROWS + row]);
    uint4 o;
    o.x = pack_h2(__float2half_rn(acc[0] * inv), __float2half_rn(acc[1] * inv));
    o.y = pack_h2(__float2half_rn(acc[2] * inv), __float2half_rn(acc[3] * inv));
    o.z = pack_h2(__float2half_rn(acc[4] * inv), __float2half_rn(acc[5] * inv));
    o.w = pack_h2(__float2half_rn(acc[6] * inv), __float2half_rn(acc[7] * inv));
    *reinterpret_cast<uint4*>(g_ch + row * D + c8) = o;
}

// ---------------------------------------------------------------------------
// Launch
// ---------------------------------------------------------------------------
extern "C" void kernel_launch(void* const* d_in, const int* in_sizes, int n_in,
                              void* d_out, int out_size)
{
    const float* x      = (const float*)d_in[0];
    const float* W_qkv  = (const float*)d_in[1];
    const float* b_qkv  = (const float*)d_in[2];
    const float* W_proj = (const float*)d_in[3];
    const float* b_proj = (const float*)d_in[4];
    float* out = (float*)d_out;

    __half *xh, *ch, *wqh, *wph;
    cudaGetSymbolAddress((void**)&xh,  g_xh);
    cudaGetSymbolAddress((void**)&ch,  g_ch);
    cudaGetSymbolAddress((void**)&wqh, g_wqh);
    cudaGetSymbolAddress((void**)&wph, g_wph);

    cudaFuncSetAttribute(attn_kernel,
                         cudaFuncAttributeMaxDynamicSharedMemorySize,
                         ATTN_SMEM_BYTES);
    cudaFuncSetAttribute(gemm_1t_kernel,
                         cudaFuncAttributeMaxDynamicSharedMemorySize,
                         QKV_SMEM_BYTES);

    // 0) merged prep
    prep_kernel<<<4224, 256>>>(x, W_qkv, W_proj);

    // 1) QKV projection (fp16 1-term, 4-stage, 1 barrier/K-step)
    gemm_1t_kernel<<<dim3(N_QKV / 128, MROWS / 128), 256, QKV_SMEM_BYTES>>>(
        xh, wqh, b_qkv, nullptr, N_QKV, 0);

    // 2) FA2 causal attention (split-KV x3, fp16 partials)
    attn_kernel<<<768, 256, ATTN_SMEM_BYTES>>>();

    // 3) combine partials -> ctx plane
    combine_kernel<<<(MROWS * D / 8) / 256, 256>>>();

    // 4) Output projection (fp16 1-term, 4-stage), fp32 out
    gemm_1t_kernel<<<dim3(D / 128, MROWS / 128), 256, QKV_SMEM_BYTES>>>(
        ch, wph, b_proj, out, D, 1);
}

// round 15
// speedup vs baseline: 1.5328x; 1.5328x over previous
#include <cuda_runtime.h>
#include <cuda_fp16.h>
#include <cstdint>
#include <cstddef>

// Problem constants
#define D      256
#define NB     4
#define TSEQ   4096
#define MROWS  (NB * TSEQ)          // 16384
#define N_QKV  (3 * D)              // 768
#define SCALE  0.0625f              // 1/sqrt(256)

// Scratch (device globals — no allocation allowed)
__device__ __half g_qkv[(size_t)MROWS * N_QKV];    // qkv fp16 (q prescaled)
__device__ __half g_xh[(size_t)MROWS * D];         // x fp16
__device__ __half g_ch[(size_t)MROWS * D];         // ctx fp16
__device__ __half g_wqh[(size_t)N_QKV * D];        // W_qkv^T [n][k]
__device__ __half g_wph[(size_t)D * D];            // W_proj^T [n][k]
__device__ float g_Op[(size_t)3 * MROWS * D];      // partial O (3 slots, fp32)
__device__ float g_lp[(size_t)3 * MROWS];          // partial l

// ---------------------------------------------------------------------------
// helpers
// ---------------------------------------------------------------------------
__device__ __forceinline__ uint32_t smem_u32(const void* p) {
    return (uint32_t)__cvta_generic_to_shared(p);
}
__device__ __forceinline__ void ldsm4(uint32_t r[4], uint32_t addr) {
    asm volatile("ldmatrix.sync.aligned.m8n8.x4.shared.b16 {%0,%1,%2,%3}, [%4];"
        : "=r"(r[0]), "=r"(r[1]), "=r"(r[2]), "=r"(r[3]) : "r"(addr));
}
__device__ __forceinline__ void ldsm4t(uint32_t r[4], uint32_t addr) {
    asm volatile("ldmatrix.sync.aligned.m8n8.x4.trans.shared.b16 {%0,%1,%2,%3}, [%4];"
        : "=r"(r[0]), "=r"(r[1]), "=r"(r[2]), "=r"(r[3]) : "r"(addr));
}
__device__ __forceinline__ void mma16816(float d[4], const uint32_t a[4],
                                         uint32_t b0, uint32_t b1) {
    asm volatile(
        "mma.sync.aligned.m16n8k16.row.col.f32.f16.f16.f32 "
        "{%0,%1,%2,%3},{%4,%5,%6,%7},{%8,%9},{%0,%1,%2,%3};"
        : "+f"(d[0]), "+f"(d[1]), "+f"(d[2]), "+f"(d[3])
        : "r"(a[0]), "r"(a[1]), "r"(a[2]), "r"(a[3]), "r"(b0), "r"(b1));
}
__device__ __forceinline__ uint32_t pack_h2(__half a, __half b) {
    return (uint32_t)__half_as_ushort(a) |
           ((uint32_t)__half_as_ushort(b) << 16);
}

#define CP_ASYNC16(dst, src) \
    asm volatile("cp.async.cg.shared.global [%0], [%1], 16;\n" \
                 :: "r"(dst), "l"(src))
#define CP_COMMIT()  asm volatile("cp.async.commit_group;\n" ::)
#define CP_WAIT0()   asm volatile("cp.async.wait_group 0;\n" ::)
#define CP_WAIT1()   asm volatile("cp.async.wait_group 1;\n" ::)
#define CP_WAIT2()   asm volatile("cp.async.wait_group 2;\n" ::)

// ---------------------------------------------------------------------------
// merged prep kernel: x -> fp16, transpose both weights -> fp16 [n][k]
//   blocks [0,4096): x ; [4096,4192): W_qkv ; [4192,4224): W_proj
// ---------------------------------------------------------------------------
__global__ void prep_kernel(const float* __restrict__ x,
                            const float* __restrict__ Wq,
                            const float* __restrict__ Wp)
{
    const int b = blockIdx.x;
    const int tid = threadIdx.x;
    if (b < 4096) {
        size_t idx = (size_t)b * 256 + tid;
        float4 v = reinterpret_cast<const float4*>(x)[idx];
        uint32_t h0 = pack_h2(__float2half_rn(v.x), __float2half_rn(v.y));
        uint32_t h1 = pack_h2(__float2half_rn(v.z), __float2half_rn(v.w));
        reinterpret_cast<uint2*>(g_xh)[idx] = make_uint2(h0, h1);
        return;
    }
    const bool isq = (b < 4192);
    const float* W = isq ? Wq : Wp;
    __half* th = isq ? g_wqh : g_wph;
    const int N = isq ? N_QKV : D;
    int idx = (b - (isq ? 4096 : 4192)) * 256 + tid;
    if (idx >= N * 32) return;
    int n = idx >> 5;
    int k0 = (idx & 31) * 8;
    uint32_t h[4];
    #pragma unroll
    for (int p = 0; p < 4; p++) {
        float a = W[(size_t)(k0 + 2 * p) * N + n];
        float bb = W[(size_t)(k0 + 2 * p + 1) * N + n];
        h[p] = pack_h2(__float2half_rn(a), __float2half_rn(bb));
    }
    *reinterpret_cast<uint4*>(th + (size_t)n * D + k0) = make_uint4(h[0], h[1], h[2], h[3]);
}

// ---------------------------------------------------------------------------
// QKV GEMM (fp16 1-term): qkv = xh * Wqh^T + b, q prescaled.
//   BM=128, BN=128, BK=32, 4 stages, ONE barrier per K-step, 2 CTAs/SM.
//   (R12 kernel, verbatim)
// ---------------------------------------------------------------------------
#define GST2 40
#define QA_ELEMS (128 * GST2)
#define QB_ELEMS (128 * GST2)
#define Q_STAGE (QA_ELEMS + QB_ELEMS)
#define QKV_SMEM_BYTES (4 * Q_STAGE * 2)       // 81920 B

__global__ __launch_bounds__(256, 2) void gemm_qkv_kernel(
    const __half* __restrict__ Ah_g, const __half* __restrict__ Bh_g,
    const float* __restrict__ bias)
{
    extern __shared__ __half sq[];
    const int tid  = threadIdx.x;
    const int lane = tid & 31;
    const int wid  = tid >> 5;
    const int wr   = wid >> 1;
    const int wc   = wid & 1;
    const int qr   = lane >> 2;
    const int qc   = lane & 3;

    const int m0 = blockIdx.y * 128;
    const int n0 = blockIdx.x * 128;

    const uint32_t sm_b = smem_u32(sq);

    auto issue = [&](int s, int kb) {
        const int k0 = kb * 32;
        __half* Ah_s = sq + (size_t)s * Q_STAGE;
        __half* Bh_s = Ah_s + QA_ELEMS;
        #pragma unroll
        for (int t = 0; t < 2; t++) {
            int i = tid + t * 256;
            int r = i >> 2;
            int c8 = (i & 3) * 8;
            size_t ga = (size_t)(m0 + r) * D + k0 + c8;
            size_t gbo = (size_t)(n0 + r) * D + k0 + c8;
            CP_ASYNC16(smem_u32(Ah_s + r * GST2 + c8), Ah_g + ga);
            CP_ASYNC16(smem_u32(Bh_s + r * GST2 + c8), Bh_g + gbo);
        }
        CP_COMMIT();
    };

    float acc[2][8][4];
    #pragma unroll
    for (int mt = 0; mt < 2; mt++)
        #pragma unroll
        for (int nt = 0; nt < 8; nt++)
            #pragma unroll
            for (int j = 0; j < 4; j++) acc[mt][nt][j] = 0.0f;

    const int b_row = ((lane >> 4) & 1) * 8 + (lane & 7);
    const int b_cg  = ((lane >> 3) & 1) * 8;

    issue(0, 0);
    issue(1, 1);
    #pragma unroll
    for (int kb = 0; kb < 8; kb++) {
        const int cur = kb & 3;
        if (kb + 2 < 8) issue((kb + 2) & 3, kb + 2);
        if (kb <= 5)      { CP_WAIT2(); }
        else if (kb == 6) { CP_WAIT1(); }
        else              { CP_WAIT0(); }
        __syncthreads();     // single barrier per K-step

        const uint32_t Ah_b = sm_b + (uint32_t)cur * (Q_STAGE * 2);
        const uint32_t Bh_b = Ah_b + QA_ELEMS * 2;

        #pragma unroll
        for (int ks = 0; ks < 2; ks++) {
            uint32_t ah[2][4];
            #pragma unroll
            for (int mt = 0; mt < 2; mt++) {
                int a_off = (wr * 32 + mt * 16 + (lane & 15)) * GST2
                            + (lane >> 4) * 8 + ks * 16;
                ldsm4(ah[mt], Ah_b + (uint32_t)a_off * 2);
            }
            #pragma unroll
            for (int np = 0; np < 4; np++) {
                int koff = (wc * 64 + np * 16 + b_row) * GST2 + ks * 16 + b_cg;
                uint32_t bh[4];
                ldsm4(bh, Bh_b + (uint32_t)koff * 2);
                #pragma unroll
                for (int mt = 0; mt < 2; mt++) {
                    mma16816(acc[mt][2 * np],     ah[mt], bh[0], bh[1]);
                    mma16816(acc[mt][2 * np + 1], ah[mt], bh[2], bh[3]);
                }
            }
        }
    }

    #pragma unroll
    for (int mt = 0; mt < 2; mt++) {
        const int rA = m0 + wr * 32 + mt * 16 + qr;
        const int rB = rA + 8;
        #pragma unroll
        for (int nt = 0; nt < 8; nt++) {
            const int gc = n0 + wc * 64 + nt * 8 + qc * 2;
            const float b0 = bias[gc], b1 = bias[gc + 1];
            float v00 = acc[mt][nt][0] + b0;
            float v01 = acc[mt][nt][1] + b1;
            float v10 = acc[mt][nt][2] + b0;
            float v11 = acc[mt][nt][3] + b1;
            if (gc < 256) { v00 *= SCALE; v01 *= SCALE; v10 *= SCALE; v11 *= SCALE; }
            uint32_t hA = pack_h2(__float2half_rn(v00), __float2half_rn(v01));
            uint32_t hB = pack_h2(__float2half_rn(v10), __float2half_rn(v11));
            *reinterpret_cast<uint32_t*>(g_qkv + (size_t)rA * N_QKV + gc) = hA;
            *reinterpret_cast<uint32_t*>(g_qkv + (size_t)rB * N_QKV + gc) = hB;
        }
    }
}

// ---------------------------------------------------------------------------
// Output projection GEMM (R12 structure, 3-stage, 2 barriers; now 1-term)
// ---------------------------------------------------------------------------
#define GA_ELEMS (128 * GST2)
#define GB_ELEMS (128 * GST2)
#define G2_STAGE (GA_ELEMS + GB_ELEMS)
#define GEMM_SMEM_BYTES (3 * G2_STAGE * 2)     // 61440 B

__global__ __launch_bounds__(256, 2) void gemm_proj_kernel(
    const __half* __restrict__ Ah_g, const __half* __restrict__ Bh_g,
    const float* __restrict__ bias, float* __restrict__ outp, int N)
{
    extern __shared__ __half sg[];
    const int tid  = threadIdx.x;
    const int lane = tid & 31;
    const int wid  = tid >> 5;
    const int wr   = wid >> 1;
    const int wc   = wid & 1;
    const int qr   = lane >> 2;
    const int qc   = lane & 3;

    const int m0 = blockIdx.y * 128;
    const int n0 = blockIdx.x * 128;

    const uint32_t sm_b = smem_u32(sg);

    auto issue = [&](int s, int kb) {
        const int k0 = kb * 32;
        __half* Ah_s = sg + (size_t)s * G2_STAGE;
        __half* Bh_s = Ah_s + GA_ELEMS;
        #pragma unroll
        for (int t = 0; t < 2; t++) {
            int i = tid + t * 256;
            int r = i >> 2;
            int c8 = (i & 3) * 8;
            size_t ga = (size_t)(m0 + r) * D + k0 + c8;
            size_t gbo = (size_t)(n0 + r) * D + k0 + c8;
            CP_ASYNC16(smem_u32(Ah_s + r * GST2 + c8), Ah_g + ga);
            CP_ASYNC16(smem_u32(Bh_s + r * GST2 + c8), Bh_g + gbo);
        }
        CP_COMMIT();
    };

    float acc[2][8][4];
    #pragma unroll
    for (int mt = 0; mt < 2; mt++)
        #pragma unroll
        for (int nt = 0; nt < 8; nt++)
            #pragma unroll
            for (int j = 0; j < 4; j++) acc[mt][nt][j] = 0.0f;

    const int b_row = ((lane >> 4) & 1) * 8 + (lane & 7);
    const int b_cg  = ((lane >> 3) & 1) * 8;

    issue(0, 0);
    issue(1, 1);
    #pragma unroll
    for (int kb = 0; kb < 8; kb++) {
        const int cur = kb % 3;
        if (kb + 2 < 8) issue((kb + 2) % 3, kb + 2);
        if (kb <= 5)      { CP_WAIT2(); }
        else if (kb == 6) { CP_WAIT1(); }
        else              { CP_WAIT0(); }
        __syncthreads();

        const uint32_t Ah_b = sm_b + (uint32_t)cur * (G2_STAGE * 2);
        const uint32_t Bh_b = Ah_b + GA_ELEMS * 2;

        #pragma unroll
        for (int ks = 0; ks < 2; ks++) {
            uint32_t ah[2][4];
            #pragma unroll
            for (int mt = 0; mt < 2; mt++) {
                int a_off = (wr * 32 + mt * 16 + (lane & 15)) * GST2
                            + (lane >> 4) * 8 + ks * 16;
                ldsm4(ah[mt], Ah_b + (uint32_t)a_off * 2);
            }
            #pragma unroll
            for (int np = 0; np < 4; np++) {
                int koff = (wc * 64 + np * 16 + b_row) * GST2 + ks * 16 + b_cg;
                uint32_t bh[4];
                ldsm4(bh, Bh_b + (uint32_t)koff * 2);
                #pragma unroll
                for (int mt = 0; mt < 2; mt++) {
                    mma16816(acc[mt][2 * np],     ah[mt], bh[0], bh[1]);
                    mma16816(acc[mt][2 * np + 1], ah[mt], bh[2], bh[3]);
                }
            }
        }
        __syncthreads();
    }

    #pragma unroll
    for (int mt = 0; mt < 2; mt++) {
        const int rA = m0 + wr * 32 + mt * 16 + qr;
        const int rB = rA + 8;
        #pragma unroll
        for (int nt = 0; nt < 8; nt++) {
            const int gc = n0 + wc * 64 + nt * 8 + qc * 2;
            const float b0 = bias[gc], b1 = bias[gc + 1];
            *reinterpret_cast<float2*>(outp + (size_t)rA * N + gc) =
                make_float2(acc[mt][nt][0] + b0, acc[mt][nt][1] + b1);
            *reinterpret_cast<float2*>(outp + (size_t)rB * N + gc) =
                make_float2(acc[mt][nt][2] + b0, acc[mt][nt][3] + b1);
        }
    }
}

// ---------------------------------------------------------------------------
// FA2-style fp16 flash attention (R12 verbatim), BN=64, 2 CTAs/SM, split-KV x3.
// smem: Qh/Kh/Vh 64x264 + Ps 64x72 + lred = 111 KB -> 2 CTAs/SM.
// ---------------------------------------------------------------------------
#define QST 264
#define KST 264
#define VST 264
#define PST 72
#define ATTN_SMEM_BYTES ((3 * 64 * 264 + 64 * PST) * 2 + 512)

__global__ __launch_bounds__(256, 2) void attn_kernel()
{
    extern __shared__ __half sm[];
    __half* Qh = sm;
    __half* Kh = Qh + 64 * QST;
    __half* Vh = Kh + 64 * KST;
    __half* Ps = Vh + 64 * VST;
    float* lred = reinterpret_cast<float*>(Ps + 64 * PST);   // [2][64]

    const int tid  = threadIdx.x;
    const int lane = tid & 31;
    const int wid  = tid >> 5;
    const int wr   = wid & 3;
    const int ch   = wid >> 2;
    const int qr   = lane >> 2;
    const int qc   = lane & 3;

    // LPT: heaviest q-tiles first. 768 CTAs = 64 qtiles x 4 batches x 3 parts
    const int bid   = blockIdx.x;
    const int it    = 63 - (bid / 12);
    const int inner = bid % 12;
    const int batch = inner & 3;
    const int part  = inner >> 2;             // 0..2
    const int i0    = it * 64;
    const int nch   = it + 1;
    const int base  = nch / 3, rem = nch % 3;
    const int cnt   = base + (part < rem ? 1 : 0);
    const int s_beg = part * base + (part < rem ? part : rem);
    const int s_end = s_beg + cnt;

    const size_t gb = (size_t)batch * TSEQ * N_QKV;

    auto issueK = [&](int j) {
        const __half* gk = g_qkv + gb + (size_t)j * 64 * N_QKV + 256;
        #pragma unroll
        for (int t = 0; t < 8; t++) {
            int i = tid + t * 256;
            int r = i >> 5, c = (i & 31) * 8;
            CP_ASYNC16(smem_u32(Kh + r * KST + c), gk + (size_t)r * N_QKV + c);
        }
        CP_COMMIT();
    };
    auto issueV = [&](int j) {
        const __half* gv = g_qkv + gb + (size_t)j * 64 * N_QKV + 512;
        #pragma unroll
        for (int t = 0; t < 8; t++) {
            int i = tid + t * 256;
            int r = i >> 5, c = (i & 31) * 8;
            CP_ASYNC16(smem_u32(Vh + r * VST + c), gv + (size_t)r * N_QKV + c);
        }
        CP_COMMIT();
    };

    const bool nonempty = (s_beg < s_end);

    if (nonempty) {
        const __half* gq = g_qkv + gb + (size_t)i0 * N_QKV;
        #pragma unroll
        for (int t = 0; t < 8; t++) {
            int i = tid + t * 256;
            int r = i >> 5, c = (i & 31) * 8;
            CP_ASYNC16(smem_u32(Qh + r * QST + c), gq + (size_t)r * N_QKV + c);
        }
        CP_COMMIT();
        issueK(s_beg);
        issueV(s_beg);
    }

    const uint32_t Qh_b = smem_u32(Qh);
    const uint32_t Kh_b = smem_u32(Kh);
    const uint32_t Vh_b = smem_u32(Vh);
    const uint32_t Ps_b = smem_u32(Ps);

    const int a_off = (wr * 16 + (lane & 15)) * QST + (lane >> 4) * 8;
    const int p_off = (wr * 16 + (lane & 15)) * PST + (lane >> 4) * 8;
    const int b_row = ((lane >> 4) & 1) * 8 + (lane & 7);
    const int b_cg  = ((lane >> 3) & 1) * 8;
    const int v_row = ((lane >> 3) & 1) * 8 + (lane & 7);
    const int v_cg  = (lane >> 4) * 8;

    float O[16][4];
    #pragma unroll
    for (int t = 0; t < 16; t++)
        #pragma unroll
        for (int j = 0; j < 4; j++) O[t][j] = 0.0f;
    float l0 = 0.0f, l1 = 0.0f;

    const int lr0  = wr * 16 + qr;
    const int row0 = i0 + lr0;
    const int row1 = row0 + 8;

    for (int s = s_beg; s < s_end; s++) {
        const bool hasNext = (s + 1 < s_end);

        CP_WAIT1();
        __syncthreads();

        // ---- S = Qh Kh^T ----
        float sacc[4][4];
        #pragma unroll
        for (int t = 0; t < 4; t++)
            #pragma unroll
            for (int j = 0; j < 4; j++) sacc[t][j] = 0.0f;

        #pragma unroll 8
        for (int ks = 0; ks < 16; ks++) {
            uint32_t ah[4];
            ldsm4(ah, Qh_b + (uint32_t)(a_off + ks * 16) * 2);
            #pragma unroll
            for (int tp = 0; tp < 2; tp++) {
                uint32_t koff = (uint32_t)((ch * 32 + tp * 16 + b_row) * KST
                                           + ks * 16 + b_cg) * 2;
                uint32_t bh[4];
                ldsm4(bh, Kh_b + koff);
                mma16816(sacc[2 * tp],     ah, bh[0], bh[1]);
                mma16816(sacc[2 * tp + 1], ah, bh[2], bh[3]);
            }
        }
        __syncthreads();
        if (hasNext) issueK(s + 1);

        // ---- exp (no max), causal mask on diag chunk, write P to smem ----
        const bool diag = (s == it);
        #pragma unroll
        for (int nt = 0; nt < 4; nt++) {
            const int cl = ch * 32 + nt * 8 + qc * 2;
            const int c0 = s * 64 + cl;
            float p0 = (diag && (c0     > row0)) ? 0.0f : __expf(sacc[nt][0]);
            float p1 = (diag && (c0 + 1 > row0)) ? 0.0f : __expf(sacc[nt][1]);
            float p2 = (diag && (c0     > row1)) ? 0.0f : __expf(sacc[nt][2]);
            float p3 = (diag && (c0 + 1 > row1)) ? 0.0f : __expf(sacc[nt][3]);
            l0 += p0 + p1;
            l1 += p2 + p3;
            *reinterpret_cast<uint32_t*>(Ps + lr0 * PST + cl) =
                pack_h2(__float2half_rn(p0), __float2half_rn(p1));
            *reinterpret_cast<uint32_t*>(Ps + (lr0 + 8) * PST + cl) =
                pack_h2(__float2half_rn(p2), __float2half_rn(p3));
        }

        if (hasNext) { CP_WAIT1(); } else { CP_WAIT0(); }
        __syncthreads();

        // ---- O += P V ----
        uint32_t aP[4][4];
        #pragma unroll
        for (int ks = 0; ks < 4; ks++)
            ldsm4(aP[ks], Ps_b + (uint32_t)(p_off + ks * 16) * 2);

        #pragma unroll
        for (int ks = 0; ks < 4; ks++) {
            #pragma unroll
            for (int nt = 0; nt < 8; nt++) {
                uint32_t voff = (uint32_t)((ks * 16 + v_row) * VST
                                           + ch * 128 + nt * 16 + v_cg) * 2;
                uint32_t bh[4];
                ldsm4t(bh, Vh_b + voff);
                mma16816(O[2 * nt],     aP[ks], bh[0], bh[1]);
                mma16816(O[2 * nt + 1], aP[ks], bh[2], bh[3]);
            }
        }
        __syncthreads();
        if (hasNext) issueV(s + 1);
    }

    // ---- epilogue ----
    l0 += __shfl_xor_sync(0xffffffffu, l0, 1);
    l0 += __shfl_xor_sync(0xffffffffu, l0, 2);
    l1 += __shfl_xor_sync(0xffffffffu, l1, 1);
    l1 += __shfl_xor_sync(0xffffffffu, l1, 2);
    __syncthreads();
    if (qc == 0) { lred[ch * 64 + lr0] = l0; lred[ch * 64 + lr0 + 8] = l1; }
    __syncthreads();

    float* dst = g_Op + ((size_t)part * MROWS + (size_t)batch * TSEQ) * D;
    #pragma unroll
    for (int nt = 0; nt < 16; nt++) {
        int col = ch * 128 + nt * 8 + qc * 2;
        *reinterpret_cast<float2*>(dst + (size_t)row0 * D + col) =
            make_float2(O[nt][0], O[nt][1]);
        *reinterpret_cast<float2*>(dst + (size_t)row1 * D + col) =
            make_float2(O[nt][2], O[nt][3]);
    }
    if (ch == 0 && qc == 0) {
        g_lp[(size_t)part * MROWS + batch * TSEQ + row0] = lred[lr0] + lred[64 + lr0];
        g_lp[(size_t)part * MROWS + batch * TSEQ + row1] = lred[lr0 + 8] + lred[64 + lr0 + 8];
    }
}

// ---------------------------------------------------------------------------
// combine: ctx = (O0+O1+O2)/(l0+l1+l2) -> fp16 plane
// ---------------------------------------------------------------------------
__global__ void combine_kernel()
{
    size_t idx = (size_t)blockIdx.x * 256 + threadIdx.x;
    size_t row = idx >> 6;
    int c4 = (int)(idx & 63) * 4;
    float4 a = *reinterpret_cast<const float4*>(g_Op + row * D + c4);
    #pragma unroll
    for (int sl = 1; sl < 3; sl++) {
        float4 b = *reinterpret_cast<const float4*>(
            g_Op + (size_t)sl * MROWS * D + row * D + c4);
        a.x += b.x; a.y += b.y; a.z += b.z; a.w += b.w;
    }
    float inv = 1.0f / (g_lp[row] + g_lp[MROWS + row] + g_lp[2 * (size_t)MROWS + row]);
    uint32_t h0 = pack_h2(__float2half_rn(a.x * inv), __float2half_rn(a.y * inv));
    uint32_t h1 = pack_h2(__float2half_rn(a.z * inv), __float2half_rn(a.w * inv));
    *reinterpret_cast<uint2*>(g_ch + row * D + c4) = make_uint2(h0, h1);
}

// ---------------------------------------------------------------------------
// Launch
// ---------------------------------------------------------------------------
extern "C" void kernel_launch(void* const* d_in, const int* in_sizes, int n_in,
                              void* d_out, int out_size)
{
    const float* x      = (const float*)d_in[0];
    const float* W_qkv  = (const float*)d_in[1];
    const float* b_qkv  = (const float*)d_in[2];
    const float* W_proj = (const float*)d_in[3];
    const float* b_proj = (const float*)d_in[4];
    float* out = (float*)d_out;

    __half *xh, *ch, *wqh, *wph;
    cudaGetSymbolAddress((void**)&xh,  g_xh);
    cudaGetSymbolAddress((void**)&ch,  g_ch);
    cudaGetSymbolAddress((void**)&wqh, g_wqh);
    cudaGetSymbolAddress((void**)&wph, g_wph);

    cudaFuncSetAttribute(attn_kernel,
                         cudaFuncAttributeMaxDynamicSharedMemorySize,
                         ATTN_SMEM_BYTES);
    cudaFuncSetAttribute(gemm_qkv_kernel,
                         cudaFuncAttributeMaxDynamicSharedMemorySize,
                         QKV_SMEM_BYTES);
    cudaFuncSetAttribute(gemm_proj_kernel,
                         cudaFuncAttributeMaxDynamicSharedMemorySize,
                         GEMM_SMEM_BYTES);

    // 0) merged prep: fp16 x + transpose both weights
    prep_kernel<<<4224, 256>>>(x, W_qkv, W_proj);

    // 1) QKV projection (fp16 1-term, 4-stage, 1 barrier/K-step)
    gemm_qkv_kernel<<<dim3(N_QKV / 128, MROWS / 128), 256, QKV_SMEM_BYTES>>>(
        xh, wqh, b_qkv);

    // 2) FA2 causal attention (fp16 single-term, BN=64, 2 CTAs/SM, split-KV x3)
    attn_kernel<<<768, 256, ATTN_SMEM_BYTES>>>();

    // 3) combine partials -> ctx plane
    combine_kernel<<<(MROWS * D / 4) / 256, 256>>>();

    // 4) Output projection (fp16 1-term, 3-stage), fp32 out
    gemm_proj_kernel<<<dim3(D / 128, MROWS / 128), 256, GEMM_SMEM_BYTES>>>(
        ch, wph, b_proj, out, D);
}